// round 7
// baseline (speedup 1.0000x reference)
#include <cuda_runtime.h>
#include <cstdint>

#define S 2048
#define BB 4
#define D 1024
#define H 16
#define HD 64

// Scratch (device globals — no allocations allowed)
__device__ float g_q[(size_t)BB * H * S * HD];    // 32 MB
__device__ float g_k[(size_t)BB * H * S * HD];    // 32 MB
__device__ float g_v[(size_t)BB * H * S * HD];    // 32 MB
__device__ float g_ctx[(size_t)BB * S * D];       // 32 MB

// ---------------------------------------------------------------------------
// TF32 / BF16 helpers
// ---------------------------------------------------------------------------
__device__ __forceinline__ float tf32r(float x) {
    uint32_t u;
    asm("cvt.rna.tf32.f32 %0, %1;" : "=r"(u) : "f"(x));
    return __uint_as_float(u);
}

__device__ __forceinline__ void mma_tf32(float* c, const uint32_t* a,
                                         const uint32_t* b) {
    asm volatile(
        "mma.sync.aligned.m16n8k8.row.col.f32.tf32.tf32.f32 "
        "{%0,%1,%2,%3},{%4,%5,%6,%7},{%8,%9},{%0,%1,%2,%3};"
        : "+f"(c[0]), "+f"(c[1]), "+f"(c[2]), "+f"(c[3])
        : "r"(a[0]), "r"(a[1]), "r"(a[2]), "r"(a[3]), "r"(b[0]), "r"(b[1]));
}

__device__ __forceinline__ void mma_bf16(float* c, const uint32_t* a,
                                         const uint32_t* b) {
    asm volatile(
        "mma.sync.aligned.m16n8k16.row.col.f32.bf16.bf16.f32 "
        "{%0,%1,%2,%3},{%4,%5,%6,%7},{%8,%9},{%0,%1,%2,%3};"
        : "+f"(c[0]), "+f"(c[1]), "+f"(c[2]), "+f"(c[3])
        : "r"(a[0]), "r"(a[1]), "r"(a[2]), "r"(a[3]), "r"(b[0]), "r"(b[1]));
}

// hi = truncate-to-bf16 (exact complement), lo = rn-bf16(x - hi)
__device__ __forceinline__ float hif(float a) {
    return __uint_as_float(__float_as_uint(a) & 0xFFFF0000u);
}
__device__ __forceinline__ uint32_t packhi(float a, float b) {
    return __byte_perm(__float_as_uint(a), __float_as_uint(b), 0x7632);
}
__device__ __forceinline__ uint32_t packlo(float a, float b) {
    float la = a - hif(a), lb = b - hif(b);
    uint32_t r;
    asm("cvt.rn.bf16x2.f32 %0, %1, %2;" : "=r"(r) : "f"(lb), "f"(la));
    return r;
}

// ---------------------------------------------------------------------------
// TF32 tensor-core GEMM, vectorized fragment staging.
// C[m,n] = sum_k A[m,k]*Bw[k,n], M=8192, K=1024.
// MODE 0: A = x (S,B,D); epilogue applies RoPE and scatters to g_q/g_k/g_v.
// MODE 1: A row-major; C = out (S,B,D), N=1024.
// Block 128x128, BK=16, 256 threads (8 warps, warp tile 32m x 64n).
// A-frags staged via shfl_xor(16) into float4 (1 LDS.128 per frag);
// B-frags staged as (k,k+4) float2 pairs, pitch 132 (1 LDS.64 per frag).
// ---------------------------------------------------------------------------
template <int MODE>
__global__ void __launch_bounds__(256, 2) tgemm(const float* __restrict__ A,
                                                const float* __restrict__ Bw,
                                                float* __restrict__ C,
                                                const float* __restrict__ cosb,
                                                const float* __restrict__ sinb) {
    constexpr int N = (MODE == 0) ? 3 * D : D;
    constexpr int K = D;

    __shared__ float4 Afr[2][16 * 33];   // (w*2+ks)*33 + g*4 + q
    __shared__ float2 Bfr[2][8 * 132];   // (ks*4+q)*132 + col

    const int tid = threadIdx.x;
    const int bm = blockIdx.y, bn = blockIdx.x;
    const int lane = tid & 31, wid = tid >> 5;
    const int grp = lane >> 2, q4 = lane & 3;
    const int mt0 = (wid & 3) * 2;
    const int wn = (wid >> 2) * 64;

    // ---- A staging role: warp wid stages m16-tile wid ----
    const int arl = lane >> 1;      // row within m16 tile
    const int aks = lane & 1;       // k8 half
    const int am = bm * 128 + wid * 16 + arl;
    const float* Ag;
    if (MODE == 0) {
        int b = am >> 11, s = am & 2047;
        Ag = A + ((size_t)s * BB + b) * D;
    } else {
        Ag = A + (size_t)am * D;
    }
    Ag += aks * 8;
    const int ag = arl & 7;
    const int abase = (wid * 2 + aks) * 33 + ag * 4;

    // ---- B staging role: thread stages rows (klow, klow+4) ----
    const int bkq = tid >> 5;
    const int bklow = (bkq & 3) + (bkq >> 2) * 8;
    const int bks = bklow >> 3, bq = bklow & 7;  // bq in 0..3
    const int bcol = lane * 4;
    const float* Bg = Bw + (size_t)bklow * N + bn * 128 + bcol;
    const int bbase = (bks * 4 + bq) * 132 + bcol;

    float acc[2][8][4];
#pragma unroll
    for (int i = 0; i < 2; i++)
#pragma unroll
        for (int j = 0; j < 8; j++)
#pragma unroll
            for (int l = 0; l < 4; l++) acc[i][j][l] = 0.0f;

    // ---- staging helpers ----
    auto stage = [&](int buf, float4 av0, float4 av1, float4 bv0, float4 bv1) {
        float f[8];
        f[0] = tf32r(av0.x); f[1] = tf32r(av0.y);
        f[2] = tf32r(av0.z); f[3] = tf32r(av0.w);
        f[4] = tf32r(av1.x); f[5] = tf32r(av1.y);
        f[6] = tf32r(av1.z); f[7] = tf32r(av1.w);
        float p[8];
#pragma unroll
        for (int e = 0; e < 8; e++)
            p[e] = __shfl_xor_sync(0xffffffffu, f[e], 16);
        if (arl < 8) {
            Afr[buf][abase + 0] = make_float4(f[0], p[0], f[4], p[4]);
            Afr[buf][abase + 1] = make_float4(f[1], p[1], f[5], p[5]);
        } else {
            Afr[buf][abase + 2] = make_float4(p[2], f[2], p[6], f[6]);
            Afr[buf][abase + 3] = make_float4(p[3], f[3], p[7], f[7]);
        }
        float4 w0 = make_float4(tf32r(bv0.x), tf32r(bv1.x), tf32r(bv0.y),
                                tf32r(bv1.y));
        float4 w1 = make_float4(tf32r(bv0.z), tf32r(bv1.z), tf32r(bv0.w),
                                tf32r(bv1.w));
        *(float4*)&Bfr[buf][bbase] = w0;
        *(float4*)&Bfr[buf][bbase + 2] = w1;
    };

    // ---- prologue: tile 0 -> buffer 0 ----
    {
        float4 av0 = *(const float4*)(Ag);
        float4 av1 = *(const float4*)(Ag + 4);
        float4 bv0 = *(const float4*)(Bg);
        float4 bv1 = *(const float4*)(Bg + (size_t)4 * N);
        stage(0, av0, av1, bv0, bv1);
    }
    __syncthreads();

    int buf = 0;
    for (int kt = 0; kt < K; kt += 16) {
        float4 pa0, pa1, pb0, pb1;
        const bool pf = (kt + 16) < K;
        if (pf) {
            pa0 = *(const float4*)(Ag + kt + 16);
            pa1 = *(const float4*)(Ag + kt + 20);
            pb0 = *(const float4*)(Bg + (size_t)(kt + 16) * N);
            pb1 = *(const float4*)(Bg + (size_t)(kt + 20) * N);
        }

        // ---- compute on current buffer ----
#pragma unroll
        for (int ks = 0; ks < 2; ks++) {
            float4 af[2];
            float2 bf[8];
            af[0] = Afr[buf][((mt0 + 0) * 2 + ks) * 33 + lane];
            af[1] = Afr[buf][((mt0 + 1) * 2 + ks) * 33 + lane];
#pragma unroll
            for (int na = 0; na < 8; na++)
                bf[na] = Bfr[buf][(ks * 4 + q4) * 132 + wn + na * 8 + grp];
#pragma unroll
            for (int ma = 0; ma < 2; ma++)
#pragma unroll
                for (int na = 0; na < 8; na++)
                    mma_tf32(acc[ma][na], (const uint32_t*)&af[ma],
                             (const uint32_t*)&bf[na]);
        }

        if (pf) stage(buf ^ 1, pa0, pa1, pb0, pb1);
        __syncthreads();
        buf ^= 1;
    }

    // ---- epilogue (MODE 0: fused RoPE + head scatter) ----
#pragma unroll
    for (int ma = 0; ma < 2; ma++) {
#pragma unroll
        for (int half = 0; half < 2; half++) {
            int m = bm * 128 + (wid & 3) * 32 + ma * 16 + grp + half * 8;
            int b = m >> 11, s = m & 2047;
#pragma unroll
            for (int na = 0; na < 8; na++) {
                int ncol = bn * 128 + wn + na * 8 + (q4 << 1);
                float v0 = acc[ma][na][half * 2 + 0];
                float v1 = acc[ma][na][half * 2 + 1];
                if (MODE == 0) {
                    int sec = ncol >> 10;
                    int e = ncol & 1023;
                    int h = e >> 6, d = e & 63;
                    size_t o = (((size_t)(b * H + h)) * S + s) * HD + d;
                    if (sec == 2) {
                        *(float2*)&g_v[o] = make_float2(v0, v1);
                    } else {
                        float c0 = cosb[s * HD + d];
                        float c1 = cosb[s * HD + d + 1];
                        float s0 = sinb[s * HD + d];
                        float s1 = sinb[s * HD + d + 1];
                        float o0 = v0 * c0 - v1 * s0;
                        float o1 = v1 * c1 + v0 * s1;
                        float* dst = (sec == 0) ? g_q : g_k;
                        *(float2*)&dst[o] = make_float2(o0, o1);
                    }
                } else {
                    *(float2*)&C[((size_t)s * BB + b) * D + ncol] =
                        make_float2(v0, v1);
                }
            }
        }
    }
}

// ---------------------------------------------------------------------------
// Flash attention, causal, 3-pass compensated BF16 (m16n8k16).
// (unchanged from R6 passing kernel)
// ---------------------------------------------------------------------------
#define FLB_QF_BYTES 32768           // 8w*2hl*4ks*32 lanes * 16B
#define FLB_KF_BYTES 16896           // 64 rows * 33 uint2 * 8B
#define FLB_SMEM (FLB_QF_BYTES + 2 * FLB_KF_BYTES)  // 66560

__global__ void __launch_bounds__(256, 2) flashb() {
    extern __shared__ char fsm[];
    uint4* qf = (uint4*)fsm;
    uint2* kf = (uint2*)(fsm + FLB_QF_BYTES);
    uint2* vf = (uint2*)(fsm + FLB_QF_BYTES + FLB_KF_BYTES);

    const int tid = threadIdx.x;
    const int qb = 15 - (int)blockIdx.x;  // heavy CTAs first
    const int bh = blockIdx.y;
    const int lane = tid & 31, w = tid >> 5;
    const int grp = lane >> 2, q4 = lane & 3;
    const int r0 = w * 16 + grp;

    const float* Qg = g_q + ((size_t)bh * S + (size_t)qb * 128) * HD;
    const float* Kg = g_k + (size_t)bh * S * HD;
    const float* Vg = g_v + (size_t)bh * S * HD;

    // ---- Q fill (once): coalesced float4 LDG -> hi/lo bf16x2 frag STS ----
#pragma unroll
    for (int i = 0; i < 8; i++) {
        int idx = i * 256 + tid;
        int r = idx >> 4, c4 = idx & 15;
        int d0 = c4 * 4;
        float4 qv = *(const float4*)(Qg + r * HD + d0);
        float e0 = qv.x * 0.125f, e1 = qv.y * 0.125f;
        float e2 = qv.z * 0.125f, e3 = qv.w * 0.125f;
        int wq = r >> 4, rl = r & 15, g = rl & 7, rh = rl >> 3;
        int ks = d0 >> 4, k2 = d0 & 15;
        int q = (k2 & 7) >> 1;
        int comp = ((k2 >= 8) ? 2 : 0) + rh;
        uint32_t* bhp = (uint32_t*)&qf[((wq * 2 + 0) * 4 + ks) * 32 + g * 4];
        uint32_t* blp = (uint32_t*)&qf[((wq * 2 + 1) * 4 + ks) * 32 + g * 4];
        bhp[q * 4 + comp] = packhi(e0, e1);
        bhp[(q + 1) * 4 + comp] = packhi(e2, e3);
        blp[q * 4 + comp] = packlo(e0, e1);
        blp[(q + 1) * 4 + comp] = packlo(e2, e3);
    }

    float accO[8][4];
#pragma unroll
    for (int na = 0; na < 8; na++)
#pragma unroll
        for (int j = 0; j < 4; j++) accO[na][j] = 0.0f;
    float mi[2] = {-1e30f, -1e30f};
    float li[2] = {0.0f, 0.0f};

    const int ft = tid >> 2;              // fill: token row 0..63
    const int fd0 = (tid & 3) * 16;       // fill: d chunk base

    const int nkt = 2 * qb + 2;
    for (int kb = 0; kb < nkt; kb++) {
        __syncthreads();  // prev-iter frag reads done before overwrite

        // ---- K fill: b-frags for QK (k = d, n = token) ----
        {
            const float* Kb = Kg + (size_t)kb * 64 * HD;
            const int na = ft >> 3, g = ft & 7;
#pragma unroll
            for (int j = 0; j < 4; j++) {
                int d0 = fd0 + j * 4;
                float4 kv = *(const float4*)(Kb + ft * HD + d0);
                int ks = d0 >> 4, k2 = d0 & 15;
                int q = (k2 & 7) >> 1;
                int comp = (k2 >= 8) ? 1 : 0;
                uint32_t* rh = (uint32_t*)&kf[((0 * 4 + ks) * 8 + na) * 33 + g * 4];
                uint32_t* rl = (uint32_t*)&kf[((1 * 4 + ks) * 8 + na) * 33 + g * 4];
                rh[q * 2 + comp] = packhi(kv.x, kv.y);
                rh[(q + 1) * 2 + comp] = packhi(kv.z, kv.w);
                rl[q * 2 + comp] = packlo(kv.x, kv.y);
                rl[(q + 1) * 2 + comp] = packlo(kv.z, kv.w);
            }
        }
        // ---- V fill: b-frags for PV (k = token, n = d) -> u16 scatter ----
        {
            const float* Vb = Vg + (size_t)kb * 64 * HD;
            int ks = ft >> 4, tk = ft & 15;
            int comp = (tk >= 8) ? 1 : 0;
            int q = (tk & 7) >> 1;
            int hlf = tk & 1;
#pragma unroll
            for (int j = 0; j < 4; j++) {
                int d0 = fd0 + j * 4;
                float4 vv = *(const float4*)(Vb + ft * HD + d0);
                float e[4] = {vv.x, vv.y, vv.z, vv.w};
#pragma unroll
                for (int ei = 0; ei < 4; ei++) {
                    int d = d0 + ei;
                    int na = d >> 3, g = d & 7;
                    uint16_t hb = (uint16_t)(__float_as_uint(e[ei]) >> 16);
                    float lof = e[ei] - hif(e[ei]);
                    uint16_t lb;
                    asm("cvt.rn.bf16.f32 %0, %1;" : "=h"(lb) : "f"(lof));
                    uint16_t* ph =
                        (uint16_t*)&vf[((0 * 4 + ks) * 8 + na) * 33 + g * 4 + q];
                    uint16_t* pl =
                        (uint16_t*)&vf[((1 * 4 + ks) * 8 + na) * 33 + g * 4 + q];
                    ph[comp * 2 + hlf] = hb;
                    pl[comp * 2 + hlf] = lb;
                }
            }
        }
        __syncthreads();

        // ---- QK^T (3x compensated bf16) ----
        float accS[8][4];
#pragma unroll
        for (int na = 0; na < 8; na++)
#pragma unroll
            for (int j = 0; j < 4; j++) accS[na][j] = 0.0f;

#pragma unroll
        for (int ks = 0; ks < 4; ks++) {
            uint4 qh = qf[((w * 2 + 0) * 4 + ks) * 32 + lane];
            uint4 ql = qf[((w * 2 + 1) * 4 + ks) * 32 + lane];
#pragma unroll
            for (int na = 0; na < 8; na++) {
                uint2 kh = kf[((0 * 4 + ks) * 8 + na) * 33 + lane];
                uint2 kl = kf[((1 * 4 + ks) * 8 + na) * 33 + lane];
                mma_bf16(accS[na], (const uint32_t*)&qh, (const uint32_t*)&kh);
                mma_bf16(accS[na], (const uint32_t*)&qh, (const uint32_t*)&kl);
                mma_bf16(accS[na], (const uint32_t*)&ql, (const uint32_t*)&kh);
            }
        }

        // ---- causal mask ----
        const int rowg0 = qb * 128 + r0;
        const int colbase = kb * 64;
        if (colbase + 63 > rowg0) {
#pragma unroll
            for (int na = 0; na < 8; na++) {
#pragma unroll
                for (int j = 0; j < 2; j++) {
                    int col = colbase + 8 * na + 2 * q4 + j;
                    if (col > rowg0) accS[na][j] = -1e30f;
                    if (col > rowg0 + 8) accS[na][2 + j] = -1e30f;
                }
            }
        }

        // ---- online softmax (exp in place; P stays in registers) ----
#pragma unroll
        for (int hr = 0; hr < 2; hr++) {
            float mx = -1e30f;
#pragma unroll
            for (int na = 0; na < 8; na++)
                mx = fmaxf(mx, fmaxf(accS[na][2 * hr], accS[na][2 * hr + 1]));
            mx = fmaxf(mx, __shfl_xor_sync(0xffffffffu, mx, 1));
            mx = fmaxf(mx, __shfl_xor_sync(0xffffffffu, mx, 2));
            float mnew = fmaxf(mi[hr], mx);
            float fac = __expf(mi[hr] - mnew);
            float rs = 0.0f;
#pragma unroll
            for (int na = 0; na < 8; na++) {
                float p0 = __expf(accS[na][2 * hr] - mnew);
                float p1 = __expf(accS[na][2 * hr + 1] - mnew);
                accS[na][2 * hr] = p0;
                accS[na][2 * hr + 1] = p1;
                rs += p0 + p1;
            }
            rs += __shfl_xor_sync(0xffffffffu, rs, 1);
            rs += __shfl_xor_sync(0xffffffffu, rs, 2);
            li[hr] = li[hr] * fac + rs;
            mi[hr] = mnew;
#pragma unroll
            for (int na = 0; na < 8; na++) {
                accO[na][2 * hr] *= fac;
                accO[na][2 * hr + 1] *= fac;
            }
        }

        // ---- PV (3x compensated bf16); A=P built in registers ----
#pragma unroll
        for (int ks = 0; ks < 4; ks++) {
            const float* A0 = accS[2 * ks];
            const float* A1 = accS[2 * ks + 1];
            uint32_t ah[4], al[4];
            ah[0] = packhi(A0[0], A0[1]);
            ah[1] = packhi(A0[2], A0[3]);
            ah[2] = packhi(A1[0], A1[1]);
            ah[3] = packhi(A1[2], A1[3]);
            al[0] = packlo(A0[0], A0[1]);
            al[1] = packlo(A0[2], A0[3]);
            al[2] = packlo(A1[0], A1[1]);
            al[3] = packlo(A1[2], A1[3]);
#pragma unroll
            for (int na = 0; na < 8; na++) {
                uint2 vh = vf[((0 * 4 + ks) * 8 + na) * 33 + lane];
                uint2 vl = vf[((1 * 4 + ks) * 8 + na) * 33 + lane];
                mma_bf16(accO[na], ah, (const uint32_t*)&vh);
                mma_bf16(accO[na], ah, (const uint32_t*)&vl);
                mma_bf16(accO[na], al, (const uint32_t*)&vh);
            }
        }
    }

    // ---- epilogue: normalize + write ctx (B,S,D) ----
    const int b = bh >> 4;
    const int h = bh & 15;
    const float inv0 = 1.0f / li[0];
    const float inv1 = 1.0f / li[1];
    const int rg = qb * 128 + r0;
#pragma unroll
    for (int na = 0; na < 8; na++) {
        int col = h * HD + 8 * na + 2 * q4;
        *(float2*)&g_ctx[((size_t)(b * S + rg)) * D + col] =
            make_float2(accO[na][0] * inv0, accO[na][1] * inv0);
        *(float2*)&g_ctx[((size_t)(b * S + rg + 8)) * D + col] =
            make_float2(accO[na][2] * inv1, accO[na][3] * inv1);
    }
}

// ---------------------------------------------------------------------------
extern "C" void kernel_launch(void* const* d_in, const int* in_sizes, int n_in,
                              void* d_out, int out_size) {
    (void)in_sizes; (void)n_in; (void)out_size;
    const float* x    = (const float*)d_in[0];
    // d_in[1] = attn_mask (pure causal; applied analytically)
    const float* cosb = (const float*)d_in[2];
    const float* sinb = (const float*)d_in[3];
    const float* Wqkv = (const float*)d_in[4];
    const float* Wout = (const float*)d_in[5];
    float* out = (float*)d_out;

    float* ctxp;
    cudaGetSymbolAddress((void**)&ctxp, g_ctx);

    cudaFuncSetAttribute(flashb, cudaFuncAttributeMaxDynamicSharedMemorySize,
                         FLB_SMEM);

    // 1) QKV projection + fused RoPE + head split (TF32 tensor cores)
    tgemm<0><<<dim3(24, 64), 256>>>(x, Wqkv, nullptr, cosb, sinb);
    // 2) Causal flash attention (3x compensated bf16 tensor cores)
    flashb<<<dim3(S / 128, BB * H), 256, FLB_SMEM>>>();
    // 3) Output projection (TF32 tensor cores) -> (S, B, D)
    tgemm<1><<<dim3(8, 64), 256>>>(ctxp, Wout, out, nullptr, nullptr);
}

// round 8
// speedup vs baseline: 1.2115x; 1.2115x over previous
#include <cuda_runtime.h>
#include <cstdint>

#define S 2048
#define BB 4
#define D 1024
#define H 16
#define HD 64

// Scratch (device globals — no allocations allowed)
__device__ float g_q[(size_t)BB * H * S * HD];    // 32 MB
__device__ float g_k[(size_t)BB * H * S * HD];    // 32 MB
__device__ float g_v[(size_t)BB * H * S * HD];    // 32 MB
__device__ float g_ctx[(size_t)BB * S * D];       // 32 MB
__device__ float g_x[(size_t)S * BB * D];         // 32 MB (tf32-rounded x)
__device__ float g_w1[(size_t)D * 3 * D];         // 12 MB (tf32-rounded Wqkv)
__device__ float g_w2[(size_t)D * D];             // 4 MB  (tf32-rounded Wout)

// ---------------------------------------------------------------------------
// TF32 / BF16 helpers
// ---------------------------------------------------------------------------
__device__ __forceinline__ float tf32r(float x) {
    uint32_t u;
    asm("cvt.rna.tf32.f32 %0, %1;" : "=r"(u) : "f"(x));
    return __uint_as_float(u);
}

__device__ __forceinline__ void mma_tf32(float* c, const uint32_t* a,
                                         const uint32_t* b) {
    asm volatile(
        "mma.sync.aligned.m16n8k8.row.col.f32.tf32.tf32.f32 "
        "{%0,%1,%2,%3},{%4,%5,%6,%7},{%8,%9},{%0,%1,%2,%3};"
        : "+f"(c[0]), "+f"(c[1]), "+f"(c[2]), "+f"(c[3])
        : "r"(a[0]), "r"(a[1]), "r"(a[2]), "r"(a[3]), "r"(b[0]), "r"(b[1]));
}

__device__ __forceinline__ void mma_bf16(float* c, const uint32_t* a,
                                         const uint32_t* b) {
    asm volatile(
        "mma.sync.aligned.m16n8k16.row.col.f32.bf16.bf16.f32 "
        "{%0,%1,%2,%3},{%4,%5,%6,%7},{%8,%9},{%0,%1,%2,%3};"
        : "+f"(c[0]), "+f"(c[1]), "+f"(c[2]), "+f"(c[3])
        : "r"(a[0]), "r"(a[1]), "r"(a[2]), "r"(a[3]), "r"(b[0]), "r"(b[1]));
}

// hi = truncate-to-bf16 (exact complement), lo = rn-bf16(x - hi)
__device__ __forceinline__ float hif(float a) {
    return __uint_as_float(__float_as_uint(a) & 0xFFFF0000u);
}
__device__ __forceinline__ uint32_t packhi(float a, float b) {
    return __byte_perm(__float_as_uint(a), __float_as_uint(b), 0x7632);
}
__device__ __forceinline__ uint32_t packlo(float a, float b) {
    float la = a - hif(a), lb = b - hif(b);
    uint32_t r;
    asm("cvt.rn.bf16x2.f32 %0, %1, %2;" : "=r"(r) : "f"(lb), "f"(la));
    return r;
}

// cp.async helpers (sm_80+; valid on compute_103 plain target)
__device__ __forceinline__ void cp16(void* dst, const void* src) {
    uint32_t d = (uint32_t)__cvta_generic_to_shared(dst);
    asm volatile("cp.async.cg.shared.global [%0], [%1], 16;" :: "r"(d),
                 "l"(src));
}
__device__ __forceinline__ void cp_commit() {
    asm volatile("cp.async.commit_group;" ::: "memory");
}
__device__ __forceinline__ void cp_wait2() {
    asm volatile("cp.async.wait_group 2;" ::: "memory");
}

// ---------------------------------------------------------------------------
// Pre-round inputs to tf32 (rna) — makes HMMA's bit-truncation exact.
// ---------------------------------------------------------------------------
__global__ void rnd_tf32(const float* __restrict__ in, float* __restrict__ out,
                         int n) {
    int i = (blockIdx.x * blockDim.x + threadIdx.x) * 4;
    if (i < n) {
        float4 v = *(const float4*)(in + i);
        *(float4*)(out + i) =
            make_float4(tf32r(v.x), tf32r(v.y), tf32r(v.z), tf32r(v.w));
    }
}

// ---------------------------------------------------------------------------
// TF32 tensor-core GEMM, cp.async 4-stage pipeline (operands pre-rounded).
// C[m,n] = sum_k A[m,k]*Bw[k,n], M=8192, K=1024.
// MODE 0: A = g_x (S,B,D); epilogue applies RoPE, scatters to g_q/g_k/g_v.
// MODE 1: A row-major (g_ctx, pre-rounded); C = out (S,B,D), N=1024.
// Block 128x128, BK=16, 256 threads (8 warps, warp tile 32m x 64n).
// Smem per stage: As 128x20 floats, Bs 16x136 floats (R6-verified banks).
// ---------------------------------------------------------------------------
#define GM_AS_STG 2560   // floats per A stage
#define GM_BS_STG 2176   // floats per B stage
#define GM_SMEM_BYTES ((4 * GM_AS_STG + 4 * GM_BS_STG) * 4)  // 75776

template <int MODE>
__global__ void __launch_bounds__(256, 2) tgemm(const float* __restrict__ A,
                                                const float* __restrict__ Bw,
                                                float* __restrict__ C,
                                                const float* __restrict__ cosb,
                                                const float* __restrict__ sinb) {
    constexpr int N = (MODE == 0) ? 3 * D : D;
    constexpr int K = D;

    extern __shared__ float gsm[];
    float* As = gsm;                    // [4][128][20]
    float* Bs = gsm + 4 * GM_AS_STG;    // [4][16][136]

    const int tid = threadIdx.x;
    const int bm = blockIdx.y, bn = blockIdx.x;
    const int lane = tid & 31, wid = tid >> 5;
    const int grp = lane >> 2, q4 = lane & 3;
    const int wm = (wid & 3) * 32;
    const int wn = (wid >> 2) * 64;

    // A load role: thread -> (row=tid/2, 8 cols at (tid&1)*8)
    const int arow = tid >> 1;
    const int ak = (tid & 1) << 3;
    const int m_a = bm * 128 + arow;
    const float* Ag;
    if (MODE == 0) {
        int b = m_a >> 11, s = m_a & 2047;
        Ag = A + ((size_t)s * BB + b) * D;
    } else {
        Ag = A + (size_t)m_a * D;
    }

    // B load role: thread -> rows (tid/32, +8), col (tid&31)*4
    const int bkr = tid >> 5;
    const int bcol = (tid & 31) << 2;
    const float* Bg = Bw + (size_t)bkr * N + bn * 128 + bcol;

    float acc[2][8][4];
#pragma unroll
    for (int i = 0; i < 2; i++)
#pragma unroll
        for (int j = 0; j < 8; j++)
#pragma unroll
            for (int l = 0; l < 4; l++) acc[i][j][l] = 0.0f;

    // ---- stage issue ----
    auto issue = [&](int kt, int s) {
        if (kt < K) {
            float* as = As + s * GM_AS_STG;
            float* bs = Bs + s * GM_BS_STG;
            cp16(&as[arow * 20 + ak], Ag + kt + ak);
            cp16(&as[arow * 20 + ak + 4], Ag + kt + ak + 4);
            cp16(&bs[bkr * 136 + bcol], Bg + (size_t)kt * N);
            cp16(&bs[(bkr + 8) * 136 + bcol], Bg + (size_t)(kt + 8) * N);
        }
        cp_commit();
    };

    // ---- prologue: 3 stages in flight ----
    issue(0, 0);
    issue(16, 1);
    issue(32, 2);

    for (int it = 0; it < K / 16; it++) {
        const int s = it & 3;
        cp_wait2();
        __syncthreads();

        const float* as = As + s * GM_AS_STG;
        const float* bs = Bs + s * GM_BS_STG;
#pragma unroll
        for (int ks = 0; ks < 2; ks++) {
            const int k0 = ks * 8;
            uint32_t a[2][4], b[8][2];
#pragma unroll
            for (int ma = 0; ma < 2; ma++) {
                int r = wm + ma * 16 + grp;
                a[ma][0] = __float_as_uint(as[r * 20 + k0 + q4]);
                a[ma][1] = __float_as_uint(as[(r + 8) * 20 + k0 + q4]);
                a[ma][2] = __float_as_uint(as[r * 20 + k0 + q4 + 4]);
                a[ma][3] = __float_as_uint(as[(r + 8) * 20 + k0 + q4 + 4]);
            }
#pragma unroll
            for (int na = 0; na < 8; na++) {
                int c = wn + na * 8 + grp;
                b[na][0] = __float_as_uint(bs[(k0 + q4) * 136 + c]);
                b[na][1] = __float_as_uint(bs[(k0 + q4 + 4) * 136 + c]);
            }
#pragma unroll
            for (int ma = 0; ma < 2; ma++)
#pragma unroll
                for (int na = 0; na < 8; na++) mma_tf32(acc[ma][na], a[ma], b[na]);
        }

        issue((it + 3) * 16, (it + 3) & 3);
    }

    // ---- epilogue (MODE 0: fused RoPE + head scatter) ----
#pragma unroll
    for (int ma = 0; ma < 2; ma++) {
#pragma unroll
        for (int half = 0; half < 2; half++) {
            int m = bm * 128 + wm + ma * 16 + grp + half * 8;
            int b = m >> 11, s = m & 2047;
#pragma unroll
            for (int na = 0; na < 8; na++) {
                int ncol = bn * 128 + wn + na * 8 + (q4 << 1);
                float v0 = acc[ma][na][half * 2 + 0];
                float v1 = acc[ma][na][half * 2 + 1];
                if (MODE == 0) {
                    int sec = ncol >> 10;
                    int e = ncol & 1023;
                    int h = e >> 6, d = e & 63;
                    size_t o = (((size_t)(b * H + h)) * S + s) * HD + d;
                    if (sec == 2) {
                        *(float2*)&g_v[o] = make_float2(v0, v1);
                    } else {
                        float c0 = cosb[s * HD + d];
                        float c1 = cosb[s * HD + d + 1];
                        float s0 = sinb[s * HD + d];
                        float s1 = sinb[s * HD + d + 1];
                        float o0 = v0 * c0 - v1 * s0;
                        float o1 = v1 * c1 + v0 * s1;
                        float* dst = (sec == 0) ? g_q : g_k;
                        *(float2*)&dst[o] = make_float2(o0, o1);
                    }
                } else {
                    *(float2*)&C[((size_t)s * BB + b) * D + ncol] =
                        make_float2(v0, v1);
                }
            }
        }
    }
}

// ---------------------------------------------------------------------------
// Flash attention, causal, 3-pass compensated BF16 (m16n8k16).
// (R6 passing kernel; only change: ctx written tf32-rna-rounded so tgemm<1>
// can consume it without an inline cvt.)
// ---------------------------------------------------------------------------
#define FLB_QF_BYTES 32768           // 8w*2hl*4ks*32 lanes * 16B
#define FLB_KF_BYTES 16896           // 64 rows * 33 uint2 * 8B
#define FLB_SMEM (FLB_QF_BYTES + 2 * FLB_KF_BYTES)  // 66560

__global__ void __launch_bounds__(256, 2) flashb() {
    extern __shared__ char fsm[];
    uint4* qf = (uint4*)fsm;
    uint2* kf = (uint2*)(fsm + FLB_QF_BYTES);
    uint2* vf = (uint2*)(fsm + FLB_QF_BYTES + FLB_KF_BYTES);

    const int tid = threadIdx.x;
    const int qb = 15 - (int)blockIdx.x;  // heavy CTAs first
    const int bh = blockIdx.y;
    const int lane = tid & 31, w = tid >> 5;
    const int grp = lane >> 2, q4 = lane & 3;
    const int r0 = w * 16 + grp;

    const float* Qg = g_q + ((size_t)bh * S + (size_t)qb * 128) * HD;
    const float* Kg = g_k + (size_t)bh * S * HD;
    const float* Vg = g_v + (size_t)bh * S * HD;

    // ---- Q fill (once): coalesced float4 LDG -> hi/lo bf16x2 frag STS ----
#pragma unroll
    for (int i = 0; i < 8; i++) {
        int idx = i * 256 + tid;
        int r = idx >> 4, c4 = idx & 15;
        int d0 = c4 * 4;
        float4 qv = *(const float4*)(Qg + r * HD + d0);
        float e0 = qv.x * 0.125f, e1 = qv.y * 0.125f;
        float e2 = qv.z * 0.125f, e3 = qv.w * 0.125f;
        int wq = r >> 4, rl = r & 15, g = rl & 7, rh = rl >> 3;
        int ks = d0 >> 4, k2 = d0 & 15;
        int q = (k2 & 7) >> 1;
        int comp = ((k2 >= 8) ? 2 : 0) + rh;
        uint32_t* bhp = (uint32_t*)&qf[((wq * 2 + 0) * 4 + ks) * 32 + g * 4];
        uint32_t* blp = (uint32_t*)&qf[((wq * 2 + 1) * 4 + ks) * 32 + g * 4];
        bhp[q * 4 + comp] = packhi(e0, e1);
        bhp[(q + 1) * 4 + comp] = packhi(e2, e3);
        blp[q * 4 + comp] = packlo(e0, e1);
        blp[(q + 1) * 4 + comp] = packlo(e2, e3);
    }

    float accO[8][4];
#pragma unroll
    for (int na = 0; na < 8; na++)
#pragma unroll
        for (int j = 0; j < 4; j++) accO[na][j] = 0.0f;
    float mi[2] = {-1e30f, -1e30f};
    float li[2] = {0.0f, 0.0f};

    const int ft = tid >> 2;              // fill: token row 0..63
    const int fd0 = (tid & 3) * 16;       // fill: d chunk base

    const int nkt = 2 * qb + 2;
    for (int kb = 0; kb < nkt; kb++) {
        __syncthreads();  // prev-iter frag reads done before overwrite

        // ---- K fill: b-frags for QK (k = d, n = token) ----
        {
            const float* Kb = Kg + (size_t)kb * 64 * HD;
            const int na = ft >> 3, g = ft & 7;
#pragma unroll
            for (int j = 0; j < 4; j++) {
                int d0 = fd0 + j * 4;
                float4 kv = *(const float4*)(Kb + ft * HD + d0);
                int ks = d0 >> 4, k2 = d0 & 15;
                int q = (k2 & 7) >> 1;
                int comp = (k2 >= 8) ? 1 : 0;
                uint32_t* rh = (uint32_t*)&kf[((0 * 4 + ks) * 8 + na) * 33 + g * 4];
                uint32_t* rl = (uint32_t*)&kf[((1 * 4 + ks) * 8 + na) * 33 + g * 4];
                rh[q * 2 + comp] = packhi(kv.x, kv.y);
                rh[(q + 1) * 2 + comp] = packhi(kv.z, kv.w);
                rl[q * 2 + comp] = packlo(kv.x, kv.y);
                rl[(q + 1) * 2 + comp] = packlo(kv.z, kv.w);
            }
        }
        // ---- V fill: b-frags for PV (k = token, n = d) -> u16 scatter ----
        {
            const float* Vb = Vg + (size_t)kb * 64 * HD;
            int ks = ft >> 4, tk = ft & 15;
            int comp = (tk >= 8) ? 1 : 0;
            int q = (tk & 7) >> 1;
            int hlf = tk & 1;
#pragma unroll
            for (int j = 0; j < 4; j++) {
                int d0 = fd0 + j * 4;
                float4 vv = *(const float4*)(Vb + ft * HD + d0);
                float e[4] = {vv.x, vv.y, vv.z, vv.w};
#pragma unroll
                for (int ei = 0; ei < 4; ei++) {
                    int d = d0 + ei;
                    int na = d >> 3, g = d & 7;
                    uint16_t hb = (uint16_t)(__float_as_uint(e[ei]) >> 16);
                    float lof = e[ei] - hif(e[ei]);
                    uint16_t lb;
                    asm("cvt.rn.bf16.f32 %0, %1;" : "=h"(lb) : "f"(lof));
                    uint16_t* ph =
                        (uint16_t*)&vf[((0 * 4 + ks) * 8 + na) * 33 + g * 4 + q];
                    uint16_t* pl =
                        (uint16_t*)&vf[((1 * 4 + ks) * 8 + na) * 33 + g * 4 + q];
                    ph[comp * 2 + hlf] = hb;
                    pl[comp * 2 + hlf] = lb;
                }
            }
        }
        __syncthreads();

        // ---- QK^T (3x compensated bf16) ----
        float accS[8][4];
#pragma unroll
        for (int na = 0; na < 8; na++)
#pragma unroll
            for (int j = 0; j < 4; j++) accS[na][j] = 0.0f;

#pragma unroll
        for (int ks = 0; ks < 4; ks++) {
            uint4 qh = qf[((w * 2 + 0) * 4 + ks) * 32 + lane];
            uint4 ql = qf[((w * 2 + 1) * 4 + ks) * 32 + lane];
#pragma unroll
            for (int na = 0; na < 8; na++) {
                uint2 kh = kf[((0 * 4 + ks) * 8 + na) * 33 + lane];
                uint2 kl = kf[((1 * 4 + ks) * 8 + na) * 33 + lane];
                mma_bf16(accS[na], (const uint32_t*)&qh, (const uint32_t*)&kh);
                mma_bf16(accS[na], (const uint32_t*)&qh, (const uint32_t*)&kl);
                mma_bf16(accS[na], (const uint32_t*)&ql, (const uint32_t*)&kh);
            }
        }

        // ---- causal mask ----
        const int rowg0 = qb * 128 + r0;
        const int colbase = kb * 64;
        if (colbase + 63 > rowg0) {
#pragma unroll
            for (int na = 0; na < 8; na++) {
#pragma unroll
                for (int j = 0; j < 2; j++) {
                    int col = colbase + 8 * na + 2 * q4 + j;
                    if (col > rowg0) accS[na][j] = -1e30f;
                    if (col > rowg0 + 8) accS[na][2 + j] = -1e30f;
                }
            }
        }

        // ---- online softmax (exp in place; P stays in registers) ----
#pragma unroll
        for (int hr = 0; hr < 2; hr++) {
            float mx = -1e30f;
#pragma unroll
            for (int na = 0; na < 8; na++)
                mx = fmaxf(mx, fmaxf(accS[na][2 * hr], accS[na][2 * hr + 1]));
            mx = fmaxf(mx, __shfl_xor_sync(0xffffffffu, mx, 1));
            mx = fmaxf(mx, __shfl_xor_sync(0xffffffffu, mx, 2));
            float mnew = fmaxf(mi[hr], mx);
            float fac = __expf(mi[hr] - mnew);
            float rs = 0.0f;
#pragma unroll
            for (int na = 0; na < 8; na++) {
                float p0 = __expf(accS[na][2 * hr] - mnew);
                float p1 = __expf(accS[na][2 * hr + 1] - mnew);
                accS[na][2 * hr] = p0;
                accS[na][2 * hr + 1] = p1;
                rs += p0 + p1;
            }
            rs += __shfl_xor_sync(0xffffffffu, rs, 1);
            rs += __shfl_xor_sync(0xffffffffu, rs, 2);
            li[hr] = li[hr] * fac + rs;
            mi[hr] = mnew;
#pragma unroll
            for (int na = 0; na < 8; na++) {
                accO[na][2 * hr] *= fac;
                accO[na][2 * hr + 1] *= fac;
            }
        }

        // ---- PV (3x compensated bf16); A=P built in registers ----
#pragma unroll
        for (int ks = 0; ks < 4; ks++) {
            const float* A0 = accS[2 * ks];
            const float* A1 = accS[2 * ks + 1];
            uint32_t ah[4], al[4];
            ah[0] = packhi(A0[0], A0[1]);
            ah[1] = packhi(A0[2], A0[3]);
            ah[2] = packhi(A1[0], A1[1]);
            ah[3] = packhi(A1[2], A1[3]);
            al[0] = packlo(A0[0], A0[1]);
            al[1] = packlo(A0[2], A0[3]);
            al[2] = packlo(A1[0], A1[1]);
            al[3] = packlo(A1[2], A1[3]);
#pragma unroll
            for (int na = 0; na < 8; na++) {
                uint2 vh = vf[((0 * 4 + ks) * 8 + na) * 33 + lane];
                uint2 vl = vf[((1 * 4 + ks) * 8 + na) * 33 + lane];
                mma_bf16(accO[na], ah, (const uint32_t*)&vh);
                mma_bf16(accO[na], ah, (const uint32_t*)&vl);
                mma_bf16(accO[na], al, (const uint32_t*)&vh);
            }
        }
    }

    // ---- epilogue: normalize + write ctx (B,S,D), tf32-rna rounded ----
    const int b = bh >> 4;
    const int h = bh & 15;
    const float inv0 = 1.0f / li[0];
    const float inv1 = 1.0f / li[1];
    const int rg = qb * 128 + r0;
#pragma unroll
    for (int na = 0; na < 8; na++) {
        int col = h * HD + 8 * na + 2 * q4;
        *(float2*)&g_ctx[((size_t)(b * S + rg)) * D + col] =
            make_float2(tf32r(accO[na][0] * inv0), tf32r(accO[na][1] * inv0));
        *(float2*)&g_ctx[((size_t)(b * S + rg + 8)) * D + col] =
            make_float2(tf32r(accO[na][2] * inv1), tf32r(accO[na][3] * inv1));
    }
}

// ---------------------------------------------------------------------------
extern "C" void kernel_launch(void* const* d_in, const int* in_sizes, int n_in,
                              void* d_out, int out_size) {
    (void)in_sizes; (void)n_in; (void)out_size;
    const float* x    = (const float*)d_in[0];
    // d_in[1] = attn_mask (pure causal; applied analytically)
    const float* cosb = (const float*)d_in[2];
    const float* sinb = (const float*)d_in[3];
    const float* Wqkv = (const float*)d_in[4];
    const float* Wout = (const float*)d_in[5];
    float* out = (float*)d_out;

    float *ctxp, *xp, *w1p, *w2p;
    cudaGetSymbolAddress((void**)&ctxp, g_ctx);
    cudaGetSymbolAddress((void**)&xp, g_x);
    cudaGetSymbolAddress((void**)&w1p, g_w1);
    cudaGetSymbolAddress((void**)&w2p, g_w2);

    cudaFuncSetAttribute(flashb, cudaFuncAttributeMaxDynamicSharedMemorySize,
                         FLB_SMEM);
    cudaFuncSetAttribute(tgemm<0>, cudaFuncAttributeMaxDynamicSharedMemorySize,
                         GM_SMEM_BYTES);
    cudaFuncSetAttribute(tgemm<1>, cudaFuncAttributeMaxDynamicSharedMemorySize,
                         GM_SMEM_BYTES);

    // 0) Pre-round inputs to tf32 (rna) once
    rnd_tf32<<<(S * BB * D / 4 + 255) / 256, 256>>>(x, xp, S * BB * D);
    rnd_tf32<<<(3 * D * D / 4 + 255) / 256, 256>>>(Wqkv, w1p, 3 * D * D);
    rnd_tf32<<<(D * D / 4 + 255) / 256, 256>>>(Wout, w2p, D * D);

    // 1) QKV projection + fused RoPE + head split (cp.async pipeline)
    tgemm<0><<<dim3(24, 64), 256, GM_SMEM_BYTES>>>(xp, w1p, nullptr, cosb, sinb);
    // 2) Causal flash attention (3x compensated bf16 tensor cores)
    flashb<<<dim3(S / 128, BB * H), 256, FLB_SMEM>>>();
    // 3) Output projection (cp.async pipeline) -> (S, B, D)
    tgemm<1><<<dim3(8, 64), 256, GM_SMEM_BYTES>>>(ctxp, w2p, out, nullptr,
                                                  nullptr);
}